// round 16
// baseline (speedup 1.0000x reference)
#include <cuda_runtime.h>
#include <cuda_fp16.h>
#include <cstdint>

// ============================================================
// out = diag(1/(rowsum(adj)+beta)) @ (adj + diag(beta)) @ x @ W + bias
// R15->R16:
//  * kernel B: split-K x2 -> x4 (grid 512, KSPLIT=2048, NITER=64).
//    Reg ceiling caps 16 warps/SM; grid 256 only averaged 13.8. Finer
//    CTAs keep every SM at 2 resident CTAs (makespan x0.87).
//  * combine fused into B: per-m-block atomic counter, last k-slice
//    CTA combines (partials L2-hot, kernel+launch removed).
// ============================================================

#define NN 8192
#define FF 256
#define MT 64             // CTA M tile (kernel B)
#define KS 32             // K per stage (kernel B)
#define NSPLIT 4          // split-K factor
#define KSPLIT (NN / NSPLIT)   // 2048
#define NITER (KSPLIT / KS)    // 64
#define KSPA 40           // A row stride in halves (80B)
#define KSPB 264          // B row stride in halves (528B, trans-ldm conflict-free)
#define AS_STAGE (MT * KSPA)        // 2560 halves
#define AS_STAGE_B (AS_STAGE * 2)   // 5120 B
#define BS_STAGE (KS * KSPB)        // 8448 halves
#define BS_STAGE_B (BS_STAGE * 2)   // 16896 B

#define OFF_AS    0                           // 2 stages * 5120
#define OFF_BS    (2 * AS_STAGE_B)            // 10240, 4 stages * 16896
#define SMEM_TOTAL (OFF_BS + 4 * BS_STAGE_B)  // 77824 (x2 CTAs = 155648/SM)

// kernel A (single-load) layout
#define KSPX 264          // x row stride in halves (528B)
#define KSPW 72           // W row stride in halves (144B)
#define OFF_WS (64 * KSPX * 2)                       // 33792
#define SMEM_A_TOTAL (OFF_WS + 256 * KSPW * 2)       // 70656 (x2 = 141312/SM)

__device__ __align__(256) __half g_xh[NN * FF];            // x fp16
__device__ __align__(256) __half g_wh[FF * FF];            // W fp16
__device__ __align__(256) __half g_yh[NN * FF];            // y fp16 (row-major)
__device__ __align__(256) float  g_part[NSPLIT * NN * FF]; // split-K partial C
__device__ __align__(256) float  g_rs[NSPLIT * NN];        // split-K partial rowsum
__device__ int g_cnt[NN / MT];                             // per-m-block arrival counter

// ---------------- helpers ----------------
__device__ __forceinline__ uint32_t smem_u32(const void* p) {
    uint32_t a;
    asm("{ .reg .u64 t; cvta.to.shared.u64 t, %1; cvt.u32.u64 %0, t; }" : "=r"(a) : "l"(p));
    return a;
}
__device__ __forceinline__ void cp16(uint32_t dst, const void* src) {
    asm volatile("cp.async.cg.shared.global [%0], [%1], 16;" :: "r"(dst), "l"(src));
}
__device__ __forceinline__ void cp_commit() {
    asm volatile("cp.async.commit_group;" ::: "memory");
}
__device__ __forceinline__ void ldm_x4(uint32_t* r, uint32_t addr) {
    asm volatile("ldmatrix.sync.aligned.m8n8.x4.shared.b16 {%0,%1,%2,%3}, [%4];"
        : "=r"(r[0]), "=r"(r[1]), "=r"(r[2]), "=r"(r[3]) : "r"(addr));
}
__device__ __forceinline__ void ldm_x4_t(uint32_t* r, uint32_t addr) {
    asm volatile("ldmatrix.sync.aligned.m8n8.x4.trans.shared.b16 {%0,%1,%2,%3}, [%4];"
        : "=r"(r[0]), "=r"(r[1]), "=r"(r[2]), "=r"(r[3]) : "r"(addr));
}
__device__ __forceinline__ void mma_f16(float* c, const uint32_t* a, uint32_t b0, uint32_t b1) {
    asm volatile(
        "mma.sync.aligned.m16n8k16.row.col.f32.f16.f16.f32 "
        "{%0,%1,%2,%3}, {%4,%5,%6,%7}, {%8,%9}, {%0,%1,%2,%3};"
        : "+f"(c[0]), "+f"(c[1]), "+f"(c[2]), "+f"(c[3])
        : "r"(a[0]), "r"(a[1]), "r"(a[2]), "r"(a[3]), "r"(b0), "r"(b1));
}

// ---------------- pre-pass: fp32 -> fp16 for x and W ----------------
__global__ void __launch_bounds__(256) convert_kernel(const float* __restrict__ x,
                                                      const float* __restrict__ w)
{
    const int idx = blockIdx.x * 256 + threadIdx.x;   // 1 thread = 8 floats
    const int NX = NN * FF / 8;                        // 262144
    if (idx < NX) {
        const float4 v0 = *(const float4*)&x[(size_t)idx * 8];
        const float4 v1 = *(const float4*)&x[(size_t)idx * 8 + 4];
        __half2 h[4];
        h[0] = __floats2half2_rn(v0.x, v0.y); h[1] = __floats2half2_rn(v0.z, v0.w);
        h[2] = __floats2half2_rn(v1.x, v1.y); h[3] = __floats2half2_rn(v1.z, v1.w);
        *(uint4*)&g_xh[(size_t)idx * 8] = make_uint4(
            *(uint32_t*)&h[0], *(uint32_t*)&h[1], *(uint32_t*)&h[2], *(uint32_t*)&h[3]);
    } else {
        const int j = idx - NX;                        // < 8192
        const float4 v0 = *(const float4*)&w[(size_t)j * 8];
        const float4 v1 = *(const float4*)&w[(size_t)j * 8 + 4];
        __half2 h[4];
        h[0] = __floats2half2_rn(v0.x, v0.y); h[1] = __floats2half2_rn(v0.z, v0.w);
        h[2] = __floats2half2_rn(v1.x, v1.y); h[3] = __floats2half2_rn(v1.z, v1.w);
        *(uint4*)&g_wh[(size_t)j * 8] = make_uint4(
            *(uint32_t*)&h[0], *(uint32_t*)&h[1], *(uint32_t*)&h[2], *(uint32_t*)&h[3]);
    }
}

// ---------------- kernel A: y = x @ W (fp16 HMMA), single-barrier ----------------
// CTA 64m x 64n, grid (128, 4) = 512 CTAs, 256 thr, 8 warps (2m x 4n), warp 32x16.
__global__ void __launch_bounds__(256, 2) gemm_y_kernel()
{
    extern __shared__ char smem[];
    const uint32_t sb = smem_u32(smem);
    const int tid = threadIdx.x;
    const int wid = tid >> 5, lane = tid & 31;
    const int g = lane >> 2, t = lane & 3;
    const int wm = wid & 1, wn = wid >> 1;
    const int m0 = blockIdx.x * 64;
    const int n0 = blockIdx.y * 64;
    const int mt8 = lane >> 3, r8 = lane & 7;

    // ---- one cp.async burst: full x-tile [64m][256k] + W-slice [256k][64n] ----
    {
        const int xr = tid >> 5, xc = tid & 31;
        #pragma unroll
        for (int p = 0; p < 8; p++) {
            const int row = p * 8 + xr;
            cp16(sb + (uint32_t)(row * KSPX + xc * 8) * 2,
                 (const void*)(g_xh + (size_t)(m0 + row) * FF + xc * 8));
        }
        const int wr = tid >> 3, wc = tid & 7;
        #pragma unroll
        for (int p = 0; p < 8; p++) {
            const int row = p * 32 + wr;
            cp16(sb + OFF_WS + (uint32_t)(row * KSPW + wc * 8) * 2,
                 (const void*)(g_wh + (size_t)row * FF + n0 + wc * 8));
        }
    }
    cp_commit();
    asm volatile("cp.async.wait_group 0;" ::: "memory");
    __syncthreads();

    const uint32_t a_lm = sb +
        (uint32_t)(((wm * 32 + (mt8 & 1) * 8 + r8) * KSPX + (mt8 >> 1) * 8) * 2);
    const uint32_t b_lm = sb + OFF_WS +
        (uint32_t)(((r8 + (mt8 & 1) * 8) * KSPW + wn * 16 + (mt8 >> 1) * 8) * 2);

    float acc[2][2][4];
    #pragma unroll
    for (int i = 0; i < 2; i++)
        #pragma unroll
        for (int j = 0; j < 2; j++)
            #pragma unroll
            for (int q = 0; q < 4; q++) acc[i][j][q] = 0.f;

    #pragma unroll
    for (int kk = 0; kk < 16; kk++) {
        uint32_t a0[4], a1[4], bf[4];
        ldm_x4(a0, a_lm + kk * 32);
        ldm_x4(a1, a_lm + kk * 32 + 16 * KSPX * 2);
        ldm_x4_t(bf, b_lm + (uint32_t)(kk * 16 * KSPW) * 2);
        mma_f16(acc[0][0], a0, bf[0], bf[1]);
        mma_f16(acc[0][1], a0, bf[2], bf[3]);
        mma_f16(acc[1][0], a1, bf[0], bf[1]);
        mma_f16(acc[1][1], a1, bf[2], bf[3]);
    }

    #pragma unroll
    for (int mi = 0; mi < 2; mi++) {
        const int lm = wm * 32 + mi * 16 + g;
        #pragma unroll
        for (int nj = 0; nj < 2; nj++) {
            const int n = n0 + wn * 16 + nj * 8 + 2 * t;
            const float* cc = acc[mi][nj];
            *(__half2*)&g_yh[(size_t)(m0 + lm) * FF + n]     = __floats2half2_rn(cc[0], cc[1]);
            *(__half2*)&g_yh[(size_t)(m0 + lm + 8) * FF + n] = __floats2half2_rn(cc[2], cc[3]);
        }
    }
}

// ---------------- kernel B: partial C = adj[:, kslice] @ y[kslice] + fused combine ----
// 256 thr, 8 warps (2m x 4n), warp tile 32x64, CTA 64x256, split-K x4, 4-stage ring.
__global__ void __launch_bounds__(256, 2) gcn_mma_kernel(
    const float* __restrict__ adj,
    const float* __restrict__ beta,
    const float* __restrict__ bias,
    float* __restrict__ out)
{
    extern __shared__ char smem[];
    __shared__ int s_last;
    __shared__ float s_scale[MT];
    __shared__ float s_beta[MT];
    __half* As = (__half*)(smem + OFF_AS);
    const uint32_t sb = smem_u32(smem);

    const int tid = threadIdx.x;
    const int wid = tid >> 5, lane = tid & 31;
    const int g = lane >> 2, t = lane & 3;
    const int wm = wid & 1, wn = wid >> 1;      // 2 m-warps x 4 n-warps
    const int mb = blockIdx.x;
    const int m0 = mb * MT;
    const int ksl = blockIdx.y;                 // 0..3
    const int k0 = ksl * KSPLIT;

    // A: 4 threads per row, 8 floats each (KS=32)
    const int ar = tid >> 2, acq = tid & 3;
    const float* aptr = adj + (size_t)(m0 + ar) * NN + k0 + acq * 8;
    __half* const a_st = As + ar * KSPA + acq * 8;
    // B: 32 threads per k-row, contiguous 16B; 8 rows/pass, 4 passes/stage
    const int br = tid >> 5, bq = tid & 31;
    const __half* bptr = g_yh + (size_t)(k0 + br) * FF + bq * 8;
    const uint32_t b_dst = sb + OFF_BS + (br * KSPB) * 2 + bq * 16;

    const int mt8 = lane >> 3, r8 = lane & 7;
    const uint32_t a_lm = sb + OFF_AS +
        (((wm * 32 + (mt8 & 1) * 8 + r8) * KSPA + (mt8 >> 1) * 8) * 2);
    const uint32_t b_lm = sb + OFF_BS +
        (((r8 + (mt8 & 1) * 8) * KSPB + wn * 64 + (mt8 >> 1) * 8) * 2);

    float rs_local = 0.f;
    float acc[2][8][4];
    #pragma unroll
    for (int i = 0; i < 2; i++)
        #pragma unroll
        for (int j = 0; j < 8; j++)
            #pragma unroll
            for (int q = 0; q < 4; q++) acc[i][j][q] = 0.f;

    float4 ra[2][2];

    // ---- prologue: B stages 0,1,2 via cp.async; A stages 0,1 via LDG ----
    #pragma unroll
    for (int s = 0; s < 3; s++) {
        #pragma unroll
        for (int c = 0; c < 4; c++)
            cp16(b_dst + s * BS_STAGE_B + c * (8 * KSPB * 2),
                 (const void*)(bptr + ((size_t)s * KS + c * 8) * FF));
        cp_commit();
    }
    #pragma unroll
    for (int s = 0; s < 2; s++) {
        ra[s][0] = *(const float4*)(aptr + (size_t)s * KS);
        ra[s][1] = *(const float4*)(aptr + (size_t)s * KS + 4);
    }
    {   // STS A stage 0 + rowsum
        const float4 v0 = ra[0][0], v1 = ra[0][1];
        rs_local += v0.x + v0.y + v0.z + v0.w + v1.x + v1.y + v1.z + v1.w;
        __half2 h[4];
        h[0] = __floats2half2_rn(v0.x, v0.y); h[1] = __floats2half2_rn(v0.z, v0.w);
        h[2] = __floats2half2_rn(v1.x, v1.y); h[3] = __floats2half2_rn(v1.z, v1.w);
        *(uint4*)a_st = make_uint4(*(uint32_t*)&h[0], *(uint32_t*)&h[1],
                                   *(uint32_t*)&h[2], *(uint32_t*)&h[3]);
    }

    // ---- main loop (single barrier, 4-stage B ring, 2 stages in flight) ----
    for (int i = 0; i < NITER; i++) {
        const int bbuf = i & 3;

        if (i + 2 < NITER) {
            const float* ap = aptr + (size_t)(i + 2) * KS;
            ra[i & 1][0] = *(const float4*)(ap);
            ra[i & 1][1] = *(const float4*)(ap + 4);
        }

        if (i < NITER - 2)       { asm volatile("cp.async.wait_group 2;" ::: "memory"); }
        else if (i == NITER - 2) { asm volatile("cp.async.wait_group 1;" ::: "memory"); }
        else                     { asm volatile("cp.async.wait_group 0;" ::: "memory"); }
        __syncthreads();

        if (i + 1 < NITER) {   // STS A stage i+1 + rowsum
            const float4 v0 = ra[(i + 1) & 1][0], v1 = ra[(i + 1) & 1][1];
            rs_local += v0.x + v0.y + v0.z + v0.w + v1.x + v1.y + v1.z + v1.w;
            __half2 h[4];
            h[0] = __floats2half2_rn(v0.x, v0.y); h[1] = __floats2half2_rn(v0.z, v0.w);
            h[2] = __floats2half2_rn(v1.x, v1.y); h[3] = __floats2half2_rn(v1.z, v1.w);
            *(uint4*)(a_st + ((i + 1) & 1) * AS_STAGE) = make_uint4(
                *(uint32_t*)&h[0], *(uint32_t*)&h[1], *(uint32_t*)&h[2], *(uint32_t*)&h[3]);
        }
        if (i + 3 < NITER) {   // cp.async B stage i+3 into buf (i+3)&3 (== i-1, free)
            const uint32_t bd = b_dst + ((i + 3) & 3) * BS_STAGE_B;
            const __half* bp = bptr + (size_t)(i + 3) * KS * FF;
            #pragma unroll
            for (int c = 0; c < 4; c++)
                cp16(bd + c * (8 * KSPB * 2), (const void*)(bp + (size_t)c * 8 * FF));
            cp_commit();
        }

        // ---- compute stage i (warp tile 32x64, 2 kk chunks) ----
        const uint32_t aB = a_lm + (i & 1) * AS_STAGE_B;
        const uint32_t bB = b_lm + bbuf * BS_STAGE_B;
        #pragma unroll
        for (int kk = 0; kk < 2; kk++) {
            uint32_t a0[4], a1[4];
            ldm_x4(a0, aB + kk * 32);
            ldm_x4(a1, aB + kk * 32 + 16 * KSPA * 2);
            uint32_t bf[4][4];
            #pragma unroll
            for (int j = 0; j < 4; j++)
                ldm_x4_t(bf[j], bB + (uint32_t)(kk * 16 * KSPB) * 2 + j * 32);
            #pragma unroll
            for (int j = 0; j < 4; j++) {
                mma_f16(acc[0][2 * j],     a0, bf[j][0], bf[j][1]);
                mma_f16(acc[0][2 * j + 1], a0, bf[j][2], bf[j][3]);
                mma_f16(acc[1][2 * j],     a1, bf[j][0], bf[j][1]);
                mma_f16(acc[1][2 * j + 1], a1, bf[j][2], bf[j][3]);
            }
        }
    }

    // ---- partial rowsum: 4 consecutive lanes per row ----
    float rs = rs_local;
    rs += __shfl_xor_sync(0xffffffffu, rs, 1);
    rs += __shfl_xor_sync(0xffffffffu, rs, 2);
    if ((tid & 3) == 0) g_rs[(size_t)ksl * NN + m0 + ar] = rs;

    // ---- write partial C ----
    float* pout = g_part + (size_t)ksl * NN * FF;
    #pragma unroll
    for (int mi = 0; mi < 2; mi++) {
        const int lm = wm * 32 + mi * 16 + g;
        #pragma unroll
        for (int nj = 0; nj < 8; nj++) {
            const int n = wn * 64 + nj * 8 + 2 * t;
            const float* cc = acc[mi][nj];
            *(float2*)&pout[(size_t)(m0 + lm) * FF + n]     = make_float2(cc[0], cc[1]);
            *(float2*)&pout[(size_t)(m0 + lm + 8) * FF + n] = make_float2(cc[2], cc[3]);
        }
    }

    // ---- fused combine: last k-slice CTA of this m-block does it ----
    __threadfence();
    if (tid == 0) {
        const int old = atomicAdd(&g_cnt[mb], 1);
        s_last = (old == NSPLIT - 1) ? 1 : 0;
    }
    __syncthreads();
    if (s_last) {
        __threadfence();
        if (tid == 0) g_cnt[mb] = 0;   // reset for next graph replay
        if (tid < MT) {
            const int m = m0 + tid;
            const float be = beta[m];
            s_beta[tid] = be;
            s_scale[tid] = 1.0f / (g_rs[m] + g_rs[NN + m] + g_rs[2 * NN + m]
                                   + g_rs[3 * NN + m] + be);
        }
        __syncthreads();
        for (int idx = tid; idx < MT * (FF / 4); idx += 256) {
            const int mr = idx >> 6;            // 0..63
            const int n = (idx & 63) * 4;
            const size_t off = (size_t)(m0 + mr) * FF + n;
            const float4 p0 = *(const float4*)&g_part[off];
            const float4 p1 = *(const float4*)&g_part[(size_t)NN * FF + off];
            const float4 p2 = *(const float4*)&g_part[(size_t)2 * NN * FF + off];
            const float4 p3 = *(const float4*)&g_part[(size_t)3 * NN * FF + off];
            const uint2 yraw = *(const uint2*)&g_yh[off];
            const float2 ya = __half22float2(*(const __half2*)&yraw.x);
            const float2 yb = __half22float2(*(const __half2*)&yraw.y);
            const float4 bv = *(const float4*)&bias[n];
            const float sc = s_scale[mr], be = s_beta[mr];
            float4 o;
            o.x = sc * (p0.x + p1.x + p2.x + p3.x + be * ya.x) + bv.x;
            o.y = sc * (p0.y + p1.y + p2.y + p3.y + be * ya.y) + bv.y;
            o.z = sc * (p0.z + p1.z + p2.z + p3.z + be * yb.x) + bv.z;
            o.w = sc * (p0.w + p1.w + p2.w + p3.w + be * yb.y) + bv.w;
            *(float4*)&out[off] = o;
        }
    }
}

// ---------------- launch ----------------
extern "C" void kernel_launch(void* const* d_in, const int* in_sizes, int n_in,
                              void* d_out, int out_size)
{
    const float *x = nullptr, *adj = nullptr, *w = nullptr, *bias = nullptr, *beta = nullptr;
    for (int i = 0; i < n_in; i++) {
        switch (in_sizes[i]) {
            case NN * FF:   x    = (const float*)d_in[i]; break;
            case 67108864:  adj  = (const float*)d_in[i]; break;
            case FF * FF:   w    = (const float*)d_in[i]; break;
            case FF:        bias = (const float*)d_in[i]; break;
            case NN:        beta = (const float*)d_in[i]; break;
            default: break;
        }
    }
    float* out = (float*)d_out;

    cudaFuncSetAttribute(gcn_mma_kernel, cudaFuncAttributeMaxDynamicSharedMemorySize, SMEM_TOTAL);
    cudaFuncSetAttribute(gemm_y_kernel, cudaFuncAttributeMaxDynamicSharedMemorySize, SMEM_A_TOTAL);

    convert_kernel<<<(NN * FF / 8 + FF * FF / 8) / 256, 256>>>(x, w);
    gemm_y_kernel<<<dim3(NN / 64, 4), 256, SMEM_A_TOTAL>>>();
    gcn_mma_kernel<<<dim3(NN / MT, NSPLIT), 256, SMEM_TOTAL>>>(adj, beta, bias, out);
}